// round 15
// baseline (speedup 1.0000x reference)
#include <cuda_runtime.h>
#include <cstdint>

// ---------------------------------------------------------------------------
// Problem constants
// ---------------------------------------------------------------------------
#define BATCH 32
#define TIME 1024
#define IN_DIM 512
#define HIDDEN 512

#define M_TOTAL (BATCH * TIME)   // 32768
#define N_TOTAL HIDDEN           // 512
#define K_TOTAL IN_DIM           // 512

#define ALPHA_MEM 0.95122942450071400909f  // exp(-0.05)
#define ALPHA_SYN 0.81873075307798185867f  // exp(-0.2)
#define THRESHOLD 1.0f

// Scratch for I_in = spikes @ W + b : [B*T, H] = 64 MB
__device__ float g_Iin[(size_t)M_TOTAL * N_TOTAL];

typedef unsigned long long u64;

__device__ __forceinline__ void fma2(u64& d, u64 a, u64 b) {
    asm("fma.rn.f32x2 %0, %1, %2, %3;" : "=l"(d) : "l"(a), "l"(b), "l"(d));
}
__device__ __forceinline__ u64 add2(u64 a, u64 b) {
    u64 r;
    asm("add.rn.f32x2 %0, %1, %2;" : "=l"(r) : "l"(a), "l"(b));
    return r;
}

// ---------------------------------------------------------------------------
// fp32 GEMM, reference-matching semantics: each output (m,n) is ONE fp32 FMA
// chain over k = 0..511 ascending, bias added once at the end (bit-matches
// the reference; rel_err == 0.0 verified rounds 1/2/8).
//
// 128x128 CTA tile, BK=16, 256 threads, 8x8 micro-tile as 8 x 4 FFMA2.
// A staged transposed+duplicated (As2[k][m] = (a,a)) so the FFMA2 broadcast
// operand comes straight from LDS.128 — no packing movs.
// NO occupancy pledge: round 8's (256,2) pledge capped regs at 128 and
// likely forced inner-loop spills (GEMM 367 -> 444us).
// ---------------------------------------------------------------------------
#define BM 128
#define BN 128
#define BK 16
#define TM 8
#define TN 8
#define APITCH 130   // float2 pitch of As2 k-rows

__global__ __launch_bounds__(256)
void gemm_f32_kernel(const float* __restrict__ A,
                     const float* __restrict__ W,
                     const float* __restrict__ bias,
                     float* __restrict__ C)
{
    __shared__ float2 As2[BK * APITCH];      // dup pairs: As2[k*APITCH + m] = (a,a)
    __shared__ float  Bs[BK][BN + 4];

    const int bm = blockIdx.y * BM;
    const int bn = blockIdx.x * BN;
    const int tid = threadIdx.x;           // 0..255
    const int tx = tid & 15;               // n micro-tile
    const int ty = tid >> 4;               // m micro-tile

    const int arow = tid >> 2;             // 0..63
    const int acol = (tid & 3) << 2;       // 0,4,8,12
    const int brow = tid >> 5;             // 0..7
    const int bcol = (tid & 31) << 2;      // 0..124

    u64 acc[TM][TN / 2];
#pragma unroll
    for (int i = 0; i < TM; i++)
#pragma unroll
        for (int j = 0; j < TN / 2; j++)
            acc[i][j] = 0ULL;

    const float* Aptr = A + (size_t)bm * K_TOTAL;
    const float* Wptr = W + bn;

    for (int k0 = 0; k0 < K_TOTAL; k0 += BK) {
        // Load A tile; transpose + duplicate into As2
#pragma unroll
        for (int r = 0; r < 2; r++) {
            const int m = arow + r * 64;
            float4 v = *(const float4*)(Aptr + (size_t)m * K_TOTAL + k0 + acol);
            As2[(acol + 0) * APITCH + m] = make_float2(v.x, v.x);
            As2[(acol + 1) * APITCH + m] = make_float2(v.y, v.y);
            As2[(acol + 2) * APITCH + m] = make_float2(v.z, v.z);
            As2[(acol + 3) * APITCH + m] = make_float2(v.w, v.w);
        }
        // Load B tile (natural [k][n])
#pragma unroll
        for (int r = 0; r < 2; r++) {
            float4 v = *(const float4*)(Wptr + (size_t)(k0 + brow + r * 8) * N_TOTAL + bcol);
            *(float4*)(&Bs[brow + r * 8][bcol]) = v;
        }
        __syncthreads();

#pragma unroll
        for (int k = 0; k < BK; k++) {
            const ulonglong2* ap128 = (const ulonglong2*)(&As2[k * APITCH + ty * TM]);
            ulonglong2 aq0 = ap128[0];
            ulonglong2 aq1 = ap128[1];
            ulonglong2 aq2 = ap128[2];
            ulonglong2 aq3 = ap128[3];
            u64 ap[TM] = { aq0.x, aq0.y, aq1.x, aq1.y, aq2.x, aq2.y, aq3.x, aq3.y };
            ulonglong2 bq0 = *(const ulonglong2*)(&Bs[k][tx * TN]);
            ulonglong2 bq1 = *(const ulonglong2*)(&Bs[k][tx * TN + 4]);
            u64 bp0 = bq0.x, bp1 = bq0.y, bp2 = bq1.x, bp3 = bq1.y;
#pragma unroll
            for (int i = 0; i < TM; i++) {
                fma2(acc[i][0], ap[i], bp0);
                fma2(acc[i][1], ap[i], bp1);
                fma2(acc[i][2], ap[i], bp2);
                fma2(acc[i][3], ap[i], bp3);
            }
        }
        __syncthreads();
    }

    // Epilogue: packed bias add, 16B stores.
    ulonglong2 bv0 = *(const ulonglong2*)(bias + bn + tx * TN);
    ulonglong2 bv1 = *(const ulonglong2*)(bias + bn + tx * TN + 4);
#pragma unroll
    for (int i = 0; i < TM; i++) {
        float* crow = C + (size_t)(bm + ty * TM + i) * N_TOTAL + bn + tx * TN;
        ulonglong2 o0, o1;
        o0.x = add2(acc[i][0], bv0.x);
        o0.y = add2(acc[i][1], bv0.y);
        o1.x = add2(acc[i][2], bv1.x);
        o1.y = add2(acc[i][3], bv1.y);
        *(ulonglong2*)(crow) = o0;
        *(ulonglong2*)(crow + 4) = o1;
    }
}

// ---------------------------------------------------------------------------
// LIF scan: 1 neuron per thread, serial over T. 64-thread blocks -> 256
// blocks. 4-buffer ring (period 4*32 = 128 divides TIME=1024 exactly),
// prefetch distance 2 blocks (~640 cyc of compute hides the 577-cyc DRAM
// latency). Arithmetic identical to the passing versions (fmaf chain).
// ---------------------------------------------------------------------------
#define SU 32
#define NBLK (TIME / SU)   // 32 time blocks

__global__ __launch_bounds__(64)
void lif_scan_kernel(const float* __restrict__ Iin, float* __restrict__ out) {
    const int g = blockIdx.x * 64 + threadIdx.x;   // 0 .. B*H-1
    const int b = g >> 9;                          // / HIDDEN
    const int h = g & (HIDDEN - 1);

    const float* p = Iin + (size_t)b * TIME * HIDDEN + h;
    float* q = out + (size_t)b * TIME * HIDDEN + h;

    float buf[4][SU];
#pragma unroll
    for (int i = 0; i < SU; i++) buf[0][i] = __ldcs(p + (size_t)i * HIDDEN);
#pragma unroll
    for (int i = 0; i < SU; i++) buf[1][i] = __ldcs(p + (size_t)(SU + i) * HIDDEN);

    float v = 0.0f, s = 0.0f;

    // Block n lives in buf[n % 4]; while computing block n, prefetch n+2.
    for (int n = 0; n < NBLK; n += 4) {
#pragma unroll
        for (int j = 0; j < 4; j++) {
            const int blk = n + j;                 // current block
            const int pf = blk + 2;                // prefetch target
            if (pf < NBLK) {
                const size_t base = (size_t)pf * SU * HIDDEN;
#pragma unroll
                for (int i = 0; i < SU; i++)
                    buf[(pf & 3)][i] = __ldcs(p + base + (size_t)i * HIDDEN);
            }
            const size_t qbase = (size_t)blk * SU * HIDDEN;
#pragma unroll
            for (int i = 0; i < SU; i++) {
                s = fmaf(ALPHA_SYN, s, buf[j & 3][i]);
                v = fmaf(ALPHA_MEM, v, s);
                float o = (v > THRESHOLD) ? 1.0f : 0.0f;
                v -= o;
                __stcs(q + qbase + (size_t)i * HIDDEN, o);
            }
        }
    }
}

// ---------------------------------------------------------------------------
extern "C" void kernel_launch(void* const* d_in, const int* in_sizes, int n_in,
                              void* d_out, int out_size)
{
    const float* spikes = (const float*)d_in[0];  // [B, T, I]
    const float* W      = (const float*)d_in[1];  // [I, H]
    const float* bias   = (const float*)d_in[2];  // [H]
    float* out          = (float*)d_out;          // [B, T, H]

    float* Iin;
    cudaGetSymbolAddress((void**)&Iin, g_Iin);

    dim3 ggrid(N_TOTAL / BN, M_TOTAL / BM);  // (4, 256)
    gemm_f32_kernel<<<ggrid, 256>>>(spikes, W, bias, Iin);

    lif_scan_kernel<<<(BATCH * HIDDEN) / 64, 64>>>(Iin, out);
}

// round 16
// speedup vs baseline: 1.2525x; 1.2525x over previous
#include <cuda_runtime.h>
#include <cstdint>

// ---------------------------------------------------------------------------
// Problem constants
// ---------------------------------------------------------------------------
#define BATCH 32
#define TIME 1024
#define IN_DIM 512
#define HIDDEN 512

#define M_TOTAL (BATCH * TIME)   // 32768
#define N_TOTAL HIDDEN           // 512
#define K_TOTAL IN_DIM           // 512

#define ALPHA_MEM 0.95122942450071400909f  // exp(-0.05)
#define ALPHA_SYN 0.81873075307798185867f  // exp(-0.2)
#define THRESHOLD 1.0f

// Scratch for I_in = spikes @ W + b : [B*T, H] = 64 MB
__device__ float g_Iin[(size_t)M_TOTAL * N_TOTAL];

typedef unsigned long long u64;

__device__ __forceinline__ u64 pack2(float x) {
    u64 r; unsigned xi = __float_as_uint(x);
    asm("mov.b64 %0, {%1, %1};" : "=l"(r) : "r"(xi));
    return r;
}
__device__ __forceinline__ void fma2(u64& d, u64 a, u64 b) {
    asm("fma.rn.f32x2 %0, %1, %2, %3;" : "=l"(d) : "l"(a), "l"(b), "l"(d));
}
__device__ __forceinline__ u64 add2(u64 a, u64 b) {
    u64 r;
    asm("add.rn.f32x2 %0, %1, %2;" : "=l"(r) : "l"(a), "l"(b));
    return r;
}

// ---------------------------------------------------------------------------
// fp32 GEMM — EXACT round-2 version (measured 367us, rel_err 0.0).
// Reference-matching semantics: each output (m,n) is one fp32 FMA chain over
// k ascending; bias added once at the end.
// 128x128 CTA tile, BK=16, 256 threads, 8x8 micro-tile via packed FFMA2.
// ---------------------------------------------------------------------------
#define BM 128
#define BN 128
#define BK 16
#define TM 8
#define TN 8
#define PAD 4

__global__ __launch_bounds__(256)
void gemm_f32_kernel(const float* __restrict__ A,
                     const float* __restrict__ W,
                     const float* __restrict__ bias,
                     float* __restrict__ C)
{
    __shared__ float As[BK][BM + PAD];  // A transposed: As[k][m]
    __shared__ float Bs[BK][BN + PAD];

    const int bm = blockIdx.y * BM;
    const int bn = blockIdx.x * BN;
    const int tid = threadIdx.x;           // 0..255
    const int tx = tid & 15;               // n micro-tile
    const int ty = tid >> 4;               // m micro-tile

    const int arow = tid >> 2;             // 0..63
    const int acol = (tid & 3) << 2;       // 0,4,8,12
    const int brow = tid >> 5;             // 0..7
    const int bcol = (tid & 31) << 2;      // 0..124

    u64 acc[TM][TN / 2];
#pragma unroll
    for (int i = 0; i < TM; i++)
#pragma unroll
        for (int j = 0; j < TN / 2; j++)
            acc[i][j] = 0ULL;

    const float* Aptr = A + (size_t)bm * K_TOTAL;
    const float* Wptr = W + bn;

    for (int k0 = 0; k0 < K_TOTAL; k0 += BK) {
        // Load A tile (transposed into As)
#pragma unroll
        for (int r = 0; r < 2; r++) {
            float4 v = *(const float4*)(Aptr + (size_t)(arow + r * 64) * K_TOTAL + k0 + acol);
            As[acol + 0][arow + r * 64] = v.x;
            As[acol + 1][arow + r * 64] = v.y;
            As[acol + 2][arow + r * 64] = v.z;
            As[acol + 3][arow + r * 64] = v.w;
        }
        // Load B tile
#pragma unroll
        for (int r = 0; r < 2; r++) {
            float4 v = *(const float4*)(Wptr + (size_t)(k0 + brow + r * 8) * N_TOTAL + bcol);
            *(float4*)(&Bs[brow + r * 8][bcol]) = v;
        }
        __syncthreads();

#pragma unroll
        for (int k = 0; k < BK; k++) {
            float4 a0 = *(const float4*)(&As[k][ty * TM]);
            float4 a1 = *(const float4*)(&As[k][ty * TM + 4]);
            u64 ap[TM];
            ap[0] = pack2(a0.x); ap[1] = pack2(a0.y);
            ap[2] = pack2(a0.z); ap[3] = pack2(a0.w);
            ap[4] = pack2(a1.x); ap[5] = pack2(a1.y);
            ap[6] = pack2(a1.z); ap[7] = pack2(a1.w);
            ulonglong2 bq0 = *(const ulonglong2*)(&Bs[k][tx * TN]);
            ulonglong2 bq1 = *(const ulonglong2*)(&Bs[k][tx * TN + 4]);
            u64 bp0 = bq0.x, bp1 = bq0.y, bp2 = bq1.x, bp3 = bq1.y;
#pragma unroll
            for (int i = 0; i < TM; i++) {
                fma2(acc[i][0], ap[i], bp0);
                fma2(acc[i][1], ap[i], bp1);
                fma2(acc[i][2], ap[i], bp2);
                fma2(acc[i][3], ap[i], bp3);
            }
        }
        __syncthreads();
    }

    // Epilogue: packed bias add, 16B stores
    ulonglong2 bv0 = *(const ulonglong2*)(bias + bn + tx * TN);
    ulonglong2 bv1 = *(const ulonglong2*)(bias + bn + tx * TN + 4);
#pragma unroll
    for (int i = 0; i < TM; i++) {
        float* crow = C + (size_t)(bm + ty * TM + i) * N_TOTAL + bn + tx * TN;
        ulonglong2 o0, o1;
        o0.x = add2(acc[i][0], bv0.x);
        o0.y = add2(acc[i][1], bv0.y);
        o1.x = add2(acc[i][2], bv1.x);
        o1.y = add2(acc[i][3], bv1.y);
        *(ulonglong2*)(crow) = o0;
        *(ulonglong2*)(crow + 4) = o1;
    }
}

// ---------------------------------------------------------------------------
// LIF scan (round-10 version, measured 29.3us, rel_err 0.0):
// 1 neuron/thread, 64-thread blocks, 4-buffer ring with prefetch distance 2.
// ---------------------------------------------------------------------------
#define SU 32
#define NBLK (TIME / SU)   // 32 time blocks

__global__ __launch_bounds__(64)
void lif_scan_kernel(const float* __restrict__ Iin, float* __restrict__ out) {
    const int g = blockIdx.x * 64 + threadIdx.x;   // 0 .. B*H-1
    const int b = g >> 9;                          // / HIDDEN
    const int h = g & (HIDDEN - 1);

    const float* p = Iin + (size_t)b * TIME * HIDDEN + h;
    float* q = out + (size_t)b * TIME * HIDDEN + h;

    float buf[4][SU];
#pragma unroll
    for (int i = 0; i < SU; i++) buf[0][i] = __ldcs(p + (size_t)i * HIDDEN);
#pragma unroll
    for (int i = 0; i < SU; i++) buf[1][i] = __ldcs(p + (size_t)(SU + i) * HIDDEN);

    float v = 0.0f, s = 0.0f;

    for (int n = 0; n < NBLK; n += 4) {
#pragma unroll
        for (int j = 0; j < 4; j++) {
            const int blk = n + j;
            const int pf = blk + 2;
            if (pf < NBLK) {
                const size_t base = (size_t)pf * SU * HIDDEN;
#pragma unroll
                for (int i = 0; i < SU; i++)
                    buf[(pf & 3)][i] = __ldcs(p + base + (size_t)i * HIDDEN);
            }
            const size_t qbase = (size_t)blk * SU * HIDDEN;
#pragma unroll
            for (int i = 0; i < SU; i++) {
                s = fmaf(ALPHA_SYN, s, buf[j & 3][i]);
                v = fmaf(ALPHA_MEM, v, s);
                float o = (v > THRESHOLD) ? 1.0f : 0.0f;
                v -= o;
                __stcs(q + qbase + (size_t)i * HIDDEN, o);
            }
        }
    }
}

// ---------------------------------------------------------------------------
// Tiny no-op kernel: rotates the harness's ncu capture window (-s 5 -c 1)
// onto the GEMM launch instead of the scan. Deterministic, negligible cost.
// ---------------------------------------------------------------------------
__global__ void sep_kernel(float* p) {
    if (blockIdx.x == 0 && threadIdx.x == 0) p[0] = p[0];
}

// ---------------------------------------------------------------------------
extern "C" void kernel_launch(void* const* d_in, const int* in_sizes, int n_in,
                              void* d_out, int out_size)
{
    const float* spikes = (const float*)d_in[0];  // [B, T, I]
    const float* W      = (const float*)d_in[1];  // [I, H]
    const float* bias   = (const float*)d_in[2];  // [H]
    float* out          = (float*)d_out;          // [B, T, H]

    float* Iin;
    cudaGetSymbolAddress((void**)&Iin, g_Iin);

    // Launch pattern (4/call): sep, gemm, scan, sep  ->  global launch index
    // 5 (0-based) = gemm of the 2nd replay, so ncu -s 5 -c 1 captures GEMM.
    sep_kernel<<<1, 32>>>(Iin);

    dim3 ggrid(N_TOTAL / BN, M_TOTAL / BM);  // (4, 256)
    gemm_f32_kernel<<<ggrid, 256>>>(spikes, W, bias, Iin);

    lif_scan_kernel<<<(BATCH * HIDDEN) / 64, 64>>>(Iin, out);

    sep_kernel<<<1, 32>>>(Iin);
}

// round 17
// speedup vs baseline: 1.3194x; 1.0534x over previous
#include <cuda_runtime.h>
#include <cstdint>

// ---------------------------------------------------------------------------
// Problem constants
// ---------------------------------------------------------------------------
#define BATCH 32
#define TIME 1024
#define IN_DIM 512
#define HIDDEN 512

#define M_TOTAL (BATCH * TIME)   // 32768
#define N_TOTAL HIDDEN           // 512
#define K_TOTAL IN_DIM           // 512

#define ALPHA_MEM 0.95122942450071400909f  // exp(-0.05)
#define ALPHA_SYN 0.81873075307798185867f  // exp(-0.2)
#define THRESHOLD 1.0f

// Scratch for I_in = spikes @ W + b : [B*T, H] = 64 MB
__device__ float g_Iin[(size_t)M_TOTAL * N_TOTAL];

typedef unsigned long long u64;

__device__ __forceinline__ u64 pack2(float x) {
    u64 r; unsigned xi = __float_as_uint(x);
    asm("mov.b64 %0, {%1, %1};" : "=l"(r) : "r"(xi));
    return r;
}
__device__ __forceinline__ void fma2(u64& d, u64 a, u64 b) {
    asm("fma.rn.f32x2 %0, %1, %2, %3;" : "=l"(d) : "l"(a), "l"(b), "l"(d));
}
__device__ __forceinline__ u64 add2(u64 a, u64 b) {
    u64 r;
    asm("add.rn.f32x2 %0, %1, %2;" : "=l"(r) : "l"(a), "l"(b));
    return r;
}

// ---------------------------------------------------------------------------
// fp32 GEMM, reference-matching semantics (per-output fp32 FMA chain over
// ascending k; bias added once at the end; rel_err == 0.0 verified).
//
// Round-2 mainloop (measured best: 367us) + register-prefetch pipelining:
// while computing chunk c from smem, the LDGs for chunk c+1 are already in
// flight into registers (~2000 cyc of FFMA2 hides the ~600 cyc latency);
// STS happens between the two syncs. Staging slots/values identical ->
// numerics bit-identical.
// ---------------------------------------------------------------------------
#define BM 128
#define BN 128
#define BK 16
#define TM 8
#define TN 8
#define PAD 4

__global__ __launch_bounds__(256)
void gemm_f32_kernel(const float* __restrict__ A,
                     const float* __restrict__ W,
                     const float* __restrict__ bias,
                     float* __restrict__ C)
{
    __shared__ float As[BK][BM + PAD];  // A transposed: As[k][m]
    __shared__ float Bs[BK][BN + PAD];

    const int bm = blockIdx.y * BM;
    const int bn = blockIdx.x * BN;
    const int tid = threadIdx.x;           // 0..255
    const int tx = tid & 15;               // n micro-tile
    const int ty = tid >> 4;               // m micro-tile

    const int arow = tid >> 2;             // 0..63
    const int acol = (tid & 3) << 2;       // 0,4,8,12
    const int brow = tid >> 5;             // 0..7
    const int bcol = (tid & 31) << 2;      // 0..124

    u64 acc[TM][TN / 2];
#pragma unroll
    for (int i = 0; i < TM; i++)
#pragma unroll
        for (int j = 0; j < TN / 2; j++)
            acc[i][j] = 0ULL;

    const float* Aptr = A + (size_t)bm * K_TOTAL;
    const float* Wptr = W + bn;

    // ---- prologue: load chunk 0 into regs, stage to smem ----
    float4 pa[2], pb[2];
#pragma unroll
    for (int r = 0; r < 2; r++) {
        pa[r] = *(const float4*)(Aptr + (size_t)(arow + r * 64) * K_TOTAL + acol);
        pb[r] = *(const float4*)(Wptr + (size_t)(brow + r * 8) * N_TOTAL + bcol);
    }
#pragma unroll
    for (int r = 0; r < 2; r++) {
        As[acol + 0][arow + r * 64] = pa[r].x;
        As[acol + 1][arow + r * 64] = pa[r].y;
        As[acol + 2][arow + r * 64] = pa[r].z;
        As[acol + 3][arow + r * 64] = pa[r].w;
        *(float4*)(&Bs[brow + r * 8][bcol]) = pb[r];
    }
    __syncthreads();

    const int NCHUNK = K_TOTAL / BK;  // 32
    for (int c = 0; c < NCHUNK; c++) {
        // ---- issue next chunk's LDGs (hidden under this chunk's compute) ----
        if (c + 1 < NCHUNK) {
            const int k0n = (c + 1) * BK;
#pragma unroll
            for (int r = 0; r < 2; r++) {
                pa[r] = *(const float4*)(Aptr + (size_t)(arow + r * 64) * K_TOTAL + k0n + acol);
                pb[r] = *(const float4*)(Wptr + (size_t)(k0n + brow + r * 8) * N_TOTAL + bcol);
            }
        }

        // ---- compute chunk c ----
#pragma unroll
        for (int k = 0; k < BK; k++) {
            float4 a0 = *(const float4*)(&As[k][ty * TM]);
            float4 a1 = *(const float4*)(&As[k][ty * TM + 4]);
            u64 ap[TM];
            ap[0] = pack2(a0.x); ap[1] = pack2(a0.y);
            ap[2] = pack2(a0.z); ap[3] = pack2(a0.w);
            ap[4] = pack2(a1.x); ap[5] = pack2(a1.y);
            ap[6] = pack2(a1.z); ap[7] = pack2(a1.w);
            ulonglong2 bq0 = *(const ulonglong2*)(&Bs[k][tx * TN]);
            ulonglong2 bq1 = *(const ulonglong2*)(&Bs[k][tx * TN + 4]);
            u64 bp0 = bq0.x, bp1 = bq0.y, bp2 = bq1.x, bp3 = bq1.y;
#pragma unroll
            for (int i = 0; i < TM; i++) {
                fma2(acc[i][0], ap[i], bp0);
                fma2(acc[i][1], ap[i], bp1);
                fma2(acc[i][2], ap[i], bp2);
                fma2(acc[i][3], ap[i], bp3);
            }
        }
        __syncthreads();

        // ---- stage next chunk from regs ----
        if (c + 1 < NCHUNK) {
#pragma unroll
            for (int r = 0; r < 2; r++) {
                As[acol + 0][arow + r * 64] = pa[r].x;
                As[acol + 1][arow + r * 64] = pa[r].y;
                As[acol + 2][arow + r * 64] = pa[r].z;
                As[acol + 3][arow + r * 64] = pa[r].w;
                *(float4*)(&Bs[brow + r * 8][bcol]) = pb[r];
            }
            __syncthreads();
        }
    }

    // Epilogue: packed bias add, 16B stores
    ulonglong2 bv0 = *(const ulonglong2*)(bias + bn + tx * TN);
    ulonglong2 bv1 = *(const ulonglong2*)(bias + bn + tx * TN + 4);
#pragma unroll
    for (int i = 0; i < TM; i++) {
        float* crow = C + (size_t)(bm + ty * TM + i) * N_TOTAL + bn + tx * TN;
        ulonglong2 o0, o1;
        o0.x = add2(acc[i][0], bv0.x);
        o0.y = add2(acc[i][1], bv0.y);
        o1.x = add2(acc[i][2], bv1.x);
        o1.y = add2(acc[i][3], bv1.y);
        *(ulonglong2*)(crow) = o0;
        *(ulonglong2*)(crow + 4) = o1;
    }
}

// ---------------------------------------------------------------------------
// LIF scan (round-10 version, measured 29.3us, rel_err 0.0):
// 1 neuron/thread, 64-thread blocks, 4-buffer ring with prefetch distance 2.
// ---------------------------------------------------------------------------
#define SU 32
#define NBLK (TIME / SU)   // 32 time blocks

__global__ __launch_bounds__(64)
void lif_scan_kernel(const float* __restrict__ Iin, float* __restrict__ out) {
    const int g = blockIdx.x * 64 + threadIdx.x;   // 0 .. B*H-1
    const int b = g >> 9;                          // / HIDDEN
    const int h = g & (HIDDEN - 1);

    const float* p = Iin + (size_t)b * TIME * HIDDEN + h;
    float* q = out + (size_t)b * TIME * HIDDEN + h;

    float buf[4][SU];
#pragma unroll
    for (int i = 0; i < SU; i++) buf[0][i] = __ldcs(p + (size_t)i * HIDDEN);
#pragma unroll
    for (int i = 0; i < SU; i++) buf[1][i] = __ldcs(p + (size_t)(SU + i) * HIDDEN);

    float v = 0.0f, s = 0.0f;

    for (int n = 0; n < NBLK; n += 4) {
#pragma unroll
        for (int j = 0; j < 4; j++) {
            const int blk = n + j;
            const int pf = blk + 2;
            if (pf < NBLK) {
                const size_t base = (size_t)pf * SU * HIDDEN;
#pragma unroll
                for (int i = 0; i < SU; i++)
                    buf[(pf & 3)][i] = __ldcs(p + base + (size_t)i * HIDDEN);
            }
            const size_t qbase = (size_t)blk * SU * HIDDEN;
#pragma unroll
            for (int i = 0; i < SU; i++) {
                s = fmaf(ALPHA_SYN, s, buf[j & 3][i]);
                v = fmaf(ALPHA_MEM, v, s);
                float o = (v > THRESHOLD) ? 1.0f : 0.0f;
                v -= o;
                __stcs(q + qbase + (size_t)i * HIDDEN, o);
            }
        }
    }
}

// ---------------------------------------------------------------------------
extern "C" void kernel_launch(void* const* d_in, const int* in_sizes, int n_in,
                              void* d_out, int out_size)
{
    const float* spikes = (const float*)d_in[0];  // [B, T, I]
    const float* W      = (const float*)d_in[1];  // [I, H]
    const float* bias   = (const float*)d_in[2];  // [H]
    float* out          = (float*)d_out;          // [B, T, H]

    float* Iin;
    cudaGetSymbolAddress((void**)&Iin, g_Iin);

    dim3 ggrid(N_TOTAL / BN, M_TOTAL / BM);  // (4, 256)
    gemm_f32_kernel<<<ggrid, 256>>>(spikes, W, bias, Iin);

    lif_scan_kernel<<<(BATCH * HIDDEN) / 64, 64>>>(Iin, out);
}